// round 16
// baseline (speedup 1.0000x reference)
#include <cuda_runtime.h>
#include <cuda_bf16.h>
#include <cstdint>
#include <math.h>

// Problem constants (fixed shapes)
#define BB 4
#define SS 12
#define NN 4096
#define CC 64
#define HH 128
#define BS (BB*SS)              // 48
#define JC (BS*CC)              // 3072  (C-space column count)
#define OUT_ELEMS (BS*NN*HH)    // 25165824
#define A_ELEMS (NN*NN)         // 16777216

// Scratch (device globals)
__device__ __align__(16) float g_d[NN];
__device__ __align__(16) __nv_bfloat16 g_Abf[A_ELEMS];            // bf16 A
__device__ __align__(16) __nv_bfloat16 g_XdT[(size_t)JC*NN];      // bf16 Xd^T [j=bs*64+c][k]
__device__ __align__(16) float g_U[(size_t)NN*JC];                // fp32 Uneg = -d[i]*(A@Xd)[i][j]

// ---------------------------------------------------------------------------
// PTX helpers (sm_103 virtual-target legal)
// ---------------------------------------------------------------------------
__device__ __forceinline__ void cpasync16(uint32_t saddr, const void* gaddr) {
    asm volatile("cp.async.cg.shared.global [%0], [%1], 16;" :: "r"(saddr), "l"(gaddr));
}
#define CP_COMMIT() asm volatile("cp.async.commit_group;" ::: "memory")
#define CP_WAIT(n)  asm volatile("cp.async.wait_group %0;" :: "n"(n) : "memory")

#define LDSM_X4(r0,r1,r2,r3,addr) \
    asm volatile("ldmatrix.sync.aligned.m8n8.x4.shared.b16 {%0,%1,%2,%3}, [%4];" \
        : "=r"(r0), "=r"(r1), "=r"(r2), "=r"(r3) : "r"(addr))

#define MMA16816(d, a0,a1,a2,a3, b0,b1) \
    asm volatile("mma.sync.aligned.m16n8k16.row.col.f32.bf16.bf16.f32 " \
        "{%0,%1,%2,%3}, {%4,%5,%6,%7}, {%8,%9}, {%0,%1,%2,%3};" \
        : "+f"((d)[0]), "+f"((d)[1]), "+f"((d)[2]), "+f"((d)[3]) \
        : "r"(a0), "r"(a1), "r"(a2), "r"(a3), "r"(b0), "r"(b1))

// ---------------------------------------------------------------------------
// Kernel 1 (fused): rowsum -> d[i], A fp32 -> bf16, optional fp32 A tail copy.
// ---------------------------------------------------------------------------
__global__ __launch_bounds__(256) void rowconv_kernel(const float* __restrict__ A,
                                                      float* __restrict__ Atail) {
    int row = blockIdx.x;
    const float4* Arow = (const float4*)(A + (size_t)row * NN);
    uint2* Brow = (uint2*)(g_Abf + (size_t)row * NN);
    float4* Crow = Atail ? (float4*)(Atail + (size_t)row * NN) : nullptr;
    float s = 0.f;
    #pragma unroll
    for (int u = 0; u < 4; u++) {
        int idx = threadIdx.x + u * 256;
        float4 v = Arow[idx];
        s += v.x + v.y + v.z + v.w;
        alignas(8) __nv_bfloat16 b[4] = {
            __float2bfloat16(v.x), __float2bfloat16(v.y),
            __float2bfloat16(v.z), __float2bfloat16(v.w) };
        Brow[idx] = *(const uint2*)b;
        if (Crow) Crow[idx] = v;
    }
    __shared__ float red[8];
    #pragma unroll
    for (int o = 16; o > 0; o >>= 1) s += __shfl_down_sync(0xffffffffu, s, o);
    if ((threadIdx.x & 31) == 0) red[threadIdx.x >> 5] = s;
    __syncthreads();
    if (threadIdx.x < 8) {
        float t = red[threadIdx.x];
        #pragma unroll
        for (int o = 4; o > 0; o >>= 1) t += __shfl_down_sync(0xffu, t, o);
        if (threadIdx.x == 0) g_d[row] = rsqrtf(t + 1.0f);
    }
}

// ---------------------------------------------------------------------------
// Kernel 2: Xd^T[bs*64+c][k] = bf16(d[k] * x[bs,k,c])   (transpose via smem)
// ---------------------------------------------------------------------------
__global__ __launch_bounds__(256) void xd_kernel(const float* __restrict__ x) {
    __shared__ float tile[128][65];
    __shared__ float sd[128];
    int tid = threadIdx.x;
    int bs = blockIdx.x, k0 = blockIdx.y * 128;
    const float4* xb = (const float4*)(x + ((size_t)bs * NN + k0) * CC);
    #pragma unroll
    for (int u = 0; u < 8; u++) {
        int idx = tid + u * 256;            // 2048 float4 = 128 rows x 64 cols
        int row = idx >> 4, c4 = (idx & 15) * 4;
        float4 v = xb[idx];
        tile[row][c4 + 0] = v.x; tile[row][c4 + 1] = v.y;
        tile[row][c4 + 2] = v.z; tile[row][c4 + 3] = v.w;
    }
    if (tid < 128) sd[tid] = g_d[k0 + tid];
    __syncthreads();

    int c = tid >> 2, g = (tid & 3) * 32;
    alignas(16) __nv_bfloat16 ob[32];
    #pragma unroll
    for (int m = 0; m < 32; m++) {
        int kk = g + m;
        ob[m] = __float2bfloat16(sd[kk] * tile[kk][c]);
    }
    __nv_bfloat16* dst = &g_XdT[((size_t)(bs * CC + c)) * NN + k0 + g];
    #pragma unroll
    for (int q = 0; q < 4; q++) ((uint4*)dst)[q] = ((const uint4*)ob)[q];
}

// ---------------------------------------------------------------------------
// Kernel 3: HMMA GEMM1 (R7-proven config: CTA 128x128, 8 warps of 32x64,
//           K-chunk 64, 2-stage cp.async):
//           g_U[i][j] = -d[i] * (A_bf @ Xd^T)[i][j]    (fp32 store)
// ---------------------------------------------------------------------------
#define KCH 64
#define NCHUNK (NN / KCH)        // 64
#define PITCH 144                 // 64 bf16 = 128B data + 16B skew
#define TILE_BYTES (128 * PITCH)  // 18432
#define STAGE_BYTES (2 * TILE_BYTES)
#define SM_D_OFF (2 * STAGE_BYTES)          // 73728
#define SMEM_TOT (SM_D_OFF + 128 * 4)       // 74240

__global__ void __launch_bounds__(256, 2) gemm1() {
    extern __shared__ char smem[];
    const uint32_t sb = (uint32_t)__cvta_generic_to_shared(smem);
    const int tid = threadIdx.x;
    const int wid = tid >> 5, lid = tid & 31;
    const int warp_m = wid & 3, warp_n = wid >> 2;   // 4 x 2 warp grid (32x64 tiles)
    const int j0 = blockIdx.x * 128;                  // col tile (C-space j)
    const int i0 = blockIdx.y * 128;                  // row tile

    float* sD = (float*)(smem + SM_D_OFF);
    if (tid < 128) sD[tid] = g_d[i0 + tid];

    const __nv_bfloat16* Ag = g_Abf + (size_t)i0 * NN;
    const __nv_bfloat16* Bg = g_XdT + (size_t)j0 * NN;

    auto load_stage = [&](int stage, int k0) {
        uint32_t aBase = sb + stage * STAGE_BYTES;
        uint32_t bBase = aBase + TILE_BYTES;
        #pragma unroll
        for (int u = 0; u < 4; u++) {
            int c = tid + u * 256;
            int row = c >> 3, kb = c & 7;
            cpasync16(aBase + row * PITCH + kb * 16, Ag + (size_t)row * NN + k0 + kb * 8);
            cpasync16(bBase + row * PITCH + kb * 16, Bg + (size_t)row * NN + k0 + kb * 8);
        }
        CP_COMMIT();
    };

    float acc[2][8][4];
    #pragma unroll
    for (int mb = 0; mb < 2; mb++)
        #pragma unroll
        for (int nb = 0; nb < 8; nb++)
            #pragma unroll
            for (int q = 0; q < 4; q++) acc[mb][nb][q] = 0.f;

    const int o = lid >> 3, r = lid & 7;
    const int amPart = warp_m * 32 + (o & 1) * 8 + r;
    const int akPart = (o >> 1) * 8;
    const int bnPart = warp_n * 64 + (o >> 1) * 8 + r;
    const int bkPart = (o & 1) * 8;

    load_stage(0, 0);

    for (int i = 0; i < NCHUNK; i++) {
        if (i + 1 < NCHUNK) load_stage((i + 1) & 1, (i + 1) * KCH);
        if (i + 1 < NCHUNK) { CP_WAIT(1); } else { CP_WAIT(0); }
        __syncthreads();

        const uint32_t aT = sb + (i & 1) * STAGE_BYTES;
        const uint32_t bT = aT + TILE_BYTES;

        #pragma unroll
        for (int kk = 0; kk < 4; kk++) {
            uint32_t a[2][4];
            #pragma unroll
            for (int mb = 0; mb < 2; mb++) {
                uint32_t addr = aT + (amPart + mb * 16) * PITCH + (kk * 16 + akPart) * 2;
                LDSM_X4(a[mb][0], a[mb][1], a[mb][2], a[mb][3], addr);
            }
            uint32_t b[4][4];
            #pragma unroll
            for (int nb = 0; nb < 4; nb++) {
                uint32_t addr = bT + (bnPart + nb * 16) * PITCH + (kk * 16 + bkPart) * 2;
                LDSM_X4(b[nb][0], b[nb][1], b[nb][2], b[nb][3], addr);
            }
            #pragma unroll
            for (int mb = 0; mb < 2; mb++)
                #pragma unroll
                for (int n8 = 0; n8 < 8; n8++) {
                    const uint32_t* bp = &b[n8 >> 1][(n8 & 1) * 2];
                    MMA16816(acc[mb][n8], a[mb][0], a[mb][1], a[mb][2], a[mb][3],
                             bp[0], bp[1]);
                }
        }
        __syncthreads();
    }

    // epilogue: g_U = -d[i] * acc  (fp32)
    const int rq = lid >> 2, cq = (lid & 3) * 2;
    #pragma unroll
    for (int mb = 0; mb < 2; mb++) {
        #pragma unroll
        for (int half = 0; half < 2; half++) {
            int rloc = warp_m * 32 + mb * 16 + rq + half * 8;
            float nd = -sD[rloc];
            float* urow = g_U + (size_t)(i0 + rloc) * JC + j0;
            #pragma unroll
            for (int n8 = 0; n8 < 8; n8++) {
                int j = warp_n * 64 + n8 * 8 + cq;
                float2 uv;
                uv.x = nd * acc[mb][n8][half * 2 + 0];
                uv.y = nd * acc[mb][n8][half * 2 + 1];
                *(float2*)(urow + j) = uv;
            }
        }
    }
}

// ---------------------------------------------------------------------------
// Kernel 4: fused final embedding + sigmoid (all fp32, exact):
//   out[bs,n,h] = sigmoid( sum_c (x[bs,n,c] + Uneg[n][bs*64+c]) * W[h,c] )
// ---------------------------------------------------------------------------
#define VROWS 8
__global__ __launch_bounds__(128) void vemb_kernel(const float* __restrict__ x,
                                                   const float* __restrict__ W,
                                                   float* __restrict__ out) {
    __shared__ float Ws[HH * CC];
    __shared__ float vs[VROWS][CC];
    int t = threadIdx.x;
    for (int i = t; i < HH * CC; i += 128) Ws[i] = W[i];

    size_t gr0 = (size_t)blockIdx.x * VROWS;     // global row over bs*NN
    int bs = (int)(gr0 >> 12);
    int i0 = (int)(gr0 & 4095);
    const float* xb = x + gr0 * CC;
    const float* ub = g_U + (size_t)i0 * JC + bs * CC;
    for (int idx = t; idx < VROWS * CC; idx += 128) {
        int r = idx >> 6, c = idx & 63;
        vs[r][c] = xb[idx] + ub[(size_t)r * JC + c];
    }
    __syncthreads();

    float wreg[CC];
    #pragma unroll
    for (int c = 0; c < CC; c++) wreg[c] = Ws[t * CC + c];

    #pragma unroll
    for (int r = 0; r < VROWS; r++) {
        float s = 0.f;
        #pragma unroll
        for (int c = 0; c < CC; c++) s += vs[r][c] * wreg[c];
        out[(gr0 + r) * HH + t] = 1.0f / (1.0f + __expf(-s));
    }
}

// ---------------------------------------------------------------------------
extern "C" void kernel_launch(void* const* d_in, const int* in_sizes, int n_in,
                              void* d_out, int out_size) {
    const float* x = (const float*)d_in[0];
    const float* A = (const float*)d_in[1];
    const float* W = (const float*)d_in[2];
    float* out = (float*)d_out;

    cudaFuncSetAttribute(gemm1, cudaFuncAttributeMaxDynamicSharedMemorySize, SMEM_TOT);

    float* tail = (out_size >= OUT_ELEMS + A_ELEMS) ? (out + OUT_ELEMS) : nullptr;
    rowconv_kernel<<<NN, 256>>>(A, tail);
    xd_kernel<<<dim3(BS, NN / 128), 256>>>(x);

    gemm1<<<dim3(JC / 128, NN / 128), 256, SMEM_TOT>>>();

    vemb_kernel<<<(BS * NN) / VROWS, 128>>>(x, W, out);
}